// round 5
// baseline (speedup 1.0000x reference)
#include <cuda_runtime.h>
#include <cuda_fp16.h>
#include <cstdint>

#define BATCH 1024
#define CIN   512
#define HW    49
#define KDIM  2304          // 9 * 256
#define MDIM  50176         // 1024 * 49
#define NDIM  512

// Scratch (module-load allocation; legal per harness rules)
__device__ __align__(16) __half Acol_g[(size_t)MDIM * KDIM];   // [m][kk]   231 MB
__device__ __align__(16) __half Whn_g[(size_t)NDIM * KDIM];    // [i][kk]   2.3 MB (K-major)

// ---------------------------------------------------------------------------
// helpers
// ---------------------------------------------------------------------------
__device__ __forceinline__ uint32_t s2u(const void* p) {
    uint32_t a;
    asm("{ .reg .u64 t; cvta.to.shared.u64 t, %1; cvt.u32.u64 %0, t; }" : "=r"(a) : "l"(p));
    return a;
}
__device__ __forceinline__ uint32_t swz(uint32_t o) { return o ^ ((o >> 3) & 0x70); }

__device__ __forceinline__ void cpa16(uint32_t s, const void* g) {
    asm volatile("cp.async.cg.shared.global [%0], [%1], 16;" :: "r"(s), "l"(g));
}

// ---------------------------------------------------------------------------
// Phase 1a: im2col A[m=(b,np)][kk=jk*256+l] fp16.
// Each thread emits 32 halfs (4x uint4) per index decomposition.
// ---------------------------------------------------------------------------
#define XP 520

__global__ void prep_a(const float* __restrict__ x) {
    extern __shared__ float xs[];  // [49][520]
    const int b = blockIdx.x;
    const float* xb = x + (size_t)b * CIN * HW;
    for (int i = threadIdx.x; i < CIN * HW; i += blockDim.x) {
        int c = i / HW, hw = i - c * HW;
        xs[hw * XP + c] = xb[i];
    }
    __syncthreads();

    uint4* aout = (uint4*)(Acol_g + (size_t)b * HW * KDIM);
    for (int idx = threadIdx.x; idx < HW * 9 * 8; idx += blockDim.x) {
        int c8 = idx & 7;          // which 32-half chunk of l
        int r  = idx >> 3;
        int jk = r % 9;
        int np = r / 9;
        int j = jk / 3, k = jk - 3 * j;
        int n = np / 7, p = np - 7 * n;

        int pk = p + k;
        bool pv = (pk >= 1 && pk <= 7);
        int w2 = (pk + 5) % 7;
        int ha = ((n + 6) % 7) + j - 1;
        int hb = n + j - 1;
        bool av = pv && (ha >= 0) && (ha < 7);
        bool bv = pv && (hb >= 0) && (hb < 7);

        const float4* pa = (const float4*)(xs + (ha * 7 + w2) * XP + 256 + c8 * 32);
        const float4* pb = (const float4*)(xs + (hb * 7 + w2) * XP + c8 * 32);
        uint4* dst = aout + np * (KDIM / 8) + jk * 32 + c8 * 4;
#pragma unroll
        for (int q = 0; q < 4; q++) {
            float4 a0 = {0,0,0,0}, a1 = {0,0,0,0}, b0 = {0,0,0,0}, b1 = {0,0,0,0};
            if (av) { a0 = pa[2 * q]; a1 = pa[2 * q + 1]; }
            if (bv) { b0 = pb[2 * q]; b1 = pb[2 * q + 1]; }
            __half2 p0 = __floats2half2_rn(a0.x + b0.x, a0.y + b0.y);
            __half2 p1 = __floats2half2_rn(a0.z + b0.z, a0.w + b0.w);
            __half2 p2 = __floats2half2_rn(a1.x + b1.x, a1.y + b1.y);
            __half2 p3 = __floats2half2_rn(a1.z + b1.z, a1.w + b1.w);
            uint4 o;
            o.x = *reinterpret_cast<uint32_t*>(&p0);
            o.y = *reinterpret_cast<uint32_t*>(&p1);
            o.z = *reinterpret_cast<uint32_t*>(&p2);
            o.w = *reinterpret_cast<uint32_t*>(&p3);
            dst[q] = o;
        }
    }
}

// ---------------------------------------------------------------------------
// Phase 1b: Whn[i][kk=jk*256+l] = fp16( W[l][j][k][i] )   (K-major per row)
// ---------------------------------------------------------------------------
__global__ void prep_w(const float* __restrict__ W) {
    int t = blockIdx.x * blockDim.x + threadIdx.x;  // over 512 * 1152 half2
    if (t >= NDIM * (KDIM / 2)) return;
    int i   = t / (KDIM / 2);
    int kk2 = t - i * (KDIM / 2);
    int kk  = kk2 * 2;
    int jk  = kk >> 8;
    int l   = kk & 255;
    float v0 = W[(size_t)(l * 9 + jk) * NDIM + i];
    float v1 = W[(size_t)((l + 1) * 9 + jk) * NDIM + i];
    reinterpret_cast<__half2*>(Whn_g)[t] = __floats2half2_rn(v0, v1);
}

// ---------------------------------------------------------------------------
// Phase 2: GEMM out[m][i] = sum_k A[m][k] * Whn[i][k]
// mma.sync m16n8k16. BM=128 BN=256 BK=64. 8 warps (2x4), warp tile 64x64.
// ldmatrix.x4 for both operands. 2-stage cp.async double buffer, SW128 smem.
// Grid (2 bn, 392 bm): bn fast -> A-tile pairs share L2.
// ---------------------------------------------------------------------------
#define BK 64
#define NC (KDIM / BK)          // 36
#define A_BYTES (128 * BK * 2)  // 16384
#define B_BYTES (256 * BK * 2)  // 32768
#define STG_BYTES (A_BYTES + B_BYTES)
#define DSMEM (2 * STG_BYTES + 256)

__device__ __forceinline__ void load_stage(
    const __half* __restrict__ Ag, const __half* __restrict__ Bg,
    uint32_t sA, uint32_t sB, int k0, int tid)
{
#pragma unroll
    for (int q = 0; q < 4; q++) {            // A: 128 rows x 8 chunks = 1024 x 16B
        int id = tid + q * 256;
        int r = id >> 3, c = id & 7;
        cpa16(sA + swz((uint32_t)(r * 128 + c * 16)),
              Ag + (size_t)r * KDIM + k0 + c * 8);
    }
#pragma unroll
    for (int q = 0; q < 8; q++) {            // B: 256 rows x 8 chunks = 2048 x 16B
        int id = tid + q * 256;
        int r = id >> 3, c = id & 7;
        cpa16(sB + swz((uint32_t)(r * 128 + c * 16)),
              Bg + (size_t)r * KDIM + k0 + c * 8);
    }
    asm volatile("cp.async.commit_group;" ::: "memory");
}

__global__ __launch_bounds__(256) void gemm_f16(float* __restrict__ out) {
    extern __shared__ char dsm[];
    const uint32_t sbase = (s2u(dsm) + 127) & ~127u;

    const int bn   = blockIdx.x;     // 0..1
    const int bm   = blockIdx.y;     // 0..391
    const int tid  = threadIdx.x;
    const int wid  = tid >> 5;
    const int lane = tid & 31;
    const int wm   = wid >> 2;       // 0..1  (64-row slab)
    const int wn   = wid & 3;        // 0..3  (64-col slab)

    const __half* Ag = Acol_g + (size_t)bm * 128 * KDIM;
    const __half* Bg = Whn_g + (size_t)bn * 256 * KDIM;

    uint32_t sA[2], sB[2];
#pragma unroll
    for (int s = 0; s < 2; s++) {
        sA[s] = sbase + s * STG_BYTES;
        sB[s] = sbase + s * STG_BYTES + A_BYTES;
    }

    float acc[4][8][4];
#pragma unroll
    for (int a = 0; a < 4; a++)
#pragma unroll
        for (int b = 0; b < 8; b++)
#pragma unroll
            for (int c = 0; c < 4; c++) acc[a][b][c] = 0.f;

    load_stage(Ag, Bg, sA[0], sB[0], 0, tid);

    // lane addressing components
    const int a_row = wm * 64 + (lane & 15);
    const int a_kad = (lane >> 4) * 16;
    const int b_row = wn * 64 + ((lane >> 4) << 3) + (lane & 7);
    const int b_kad = ((lane >> 3) & 1) * 16;

    for (int t = 0; t < NC; t++) {
        asm volatile("cp.async.wait_group 0;" ::: "memory");
        __syncthreads();
        if (t + 1 < NC)
            load_stage(Ag, Bg, sA[(t + 1) & 1], sB[(t + 1) & 1], (t + 1) * BK, tid);

        const uint32_t cA = sA[t & 1];
        const uint32_t cB = sB[t & 1];
#pragma unroll
        for (int ks = 0; ks < 4; ks++) {
            const uint32_t kboff = ks * 32;  // 16 halfs
            uint32_t a[4][4];
#pragma unroll
            for (int mi = 0; mi < 4; mi++) {
                uint32_t full = cA + swz((uint32_t)((a_row + mi * 16) * 128 + kboff + a_kad));
                asm volatile("ldmatrix.sync.aligned.m8n8.x4.shared.b16 {%0,%1,%2,%3}, [%4];"
                             : "=r"(a[mi][0]), "=r"(a[mi][1]), "=r"(a[mi][2]), "=r"(a[mi][3])
                             : "r"(full));
            }
            uint32_t bf[4][4];
#pragma unroll
            for (int nb = 0; nb < 4; nb++) {
                uint32_t full = cB + swz((uint32_t)((b_row + nb * 16) * 128 + kboff + b_kad));
                asm volatile("ldmatrix.sync.aligned.m8n8.x4.shared.b16 {%0,%1,%2,%3}, [%4];"
                             : "=r"(bf[nb][0]), "=r"(bf[nb][1]), "=r"(bf[nb][2]), "=r"(bf[nb][3])
                             : "r"(full));
            }
#pragma unroll
            for (int mi = 0; mi < 4; mi++)
#pragma unroll
                for (int ni = 0; ni < 8; ni++) {
                    const int nb = ni >> 1, hp = (ni & 1) * 2;
                    asm volatile(
                        "mma.sync.aligned.m16n8k16.row.col.f32.f16.f16.f32 "
                        "{%0,%1,%2,%3}, {%4,%5,%6,%7}, {%8,%9}, {%0,%1,%2,%3};"
                        : "+f"(acc[mi][ni][0]), "+f"(acc[mi][ni][1]),
                          "+f"(acc[mi][ni][2]), "+f"(acc[mi][ni][3])
                        : "r"(a[mi][0]), "r"(a[mi][1]), "r"(a[mi][2]), "r"(a[mi][3]),
                          "r"(bf[nb][hp]), "r"(bf[nb][hp + 1]));
                }
        }
    }

    // Epilogue: scatter to out[(b*512 + i)*49 + np]
    const int m_base = bm * 128 + wm * 64;
    const int i_base = bn * 256 + wn * 64;
#pragma unroll
    for (int mi = 0; mi < 4; mi++) {
#pragma unroll
        for (int ni = 0; ni < 8; ni++) {
            int row0 = m_base + mi * 16 + (lane >> 2);
            int col0 = i_base + ni * 8 + (lane & 3) * 2;
#pragma unroll
            for (int h = 0; h < 2; h++) {
                int m  = row0 + h * 8;
                int b  = m / 49;
                int np = m - b * 49;
                float* o = out + (size_t)(b * NDIM + col0) * 49 + np;
                o[0]  = acc[mi][ni][h * 2 + 0];
                o[49] = acc[mi][ni][h * 2 + 1];
            }
        }
    }
}

// ---------------------------------------------------------------------------
extern "C" void kernel_launch(void* const* d_in, const int* in_sizes, int n_in,
                              void* d_out, int out_size) {
    const float* x = (const float*)d_in[0];   // (1024, 512, 7, 7)
    const float* W = (const float*)d_in[1];   // (256, 3, 3, 512)
    float* out = (float*)d_out;               // (1024, 512, 7, 7)

    cudaFuncSetAttribute(prep_a, cudaFuncAttributeMaxDynamicSharedMemorySize,
                         HW * XP * (int)sizeof(float));
    cudaFuncSetAttribute(gemm_f16, cudaFuncAttributeMaxDynamicSharedMemorySize, DSMEM);

    prep_a<<<BATCH, 512, HW * XP * sizeof(float)>>>(x);
    prep_w<<<(NDIM * (KDIM / 2) + 255) / 256, 256>>>(W);
    gemm_f16<<<dim3(NDIM / 256, MDIM / 128), 256, DSMEM>>>(out);
}

// round 6
// speedup vs baseline: 1.4030x; 1.4030x over previous
#include <cuda_runtime.h>
#include <cuda_fp16.h>
#include <cstdint>

#define BATCH 1024
#define CIN   512
#define HW    49
#define KDIM  2304          // 9 * 256
#define MDIM  50176         // 1024 * 49
#define NDIM  512

// Scratch (module-load allocation; legal per harness rules)
__device__ __align__(16) __half Acol_g[(size_t)MDIM * KDIM];   // [m][kk]   231 MB
__device__ __align__(16) __half Whn_g[(size_t)NDIM * KDIM];    // [i][kk]   2.3 MB (K-major)

// ---------------------------------------------------------------------------
// helpers
// ---------------------------------------------------------------------------
__device__ __forceinline__ uint32_t s2u(const void* p) {
    uint32_t a;
    asm("{ .reg .u64 t; cvta.to.shared.u64 t, %1; cvt.u32.u64 %0, t; }" : "=r"(a) : "l"(p));
    return a;
}
__device__ __forceinline__ uint32_t swz(uint32_t o) { return o ^ ((o >> 3) & 0x70); }

__device__ __forceinline__ void cpa16(uint32_t s, const void* g) {
    asm volatile("cp.async.cg.shared.global [%0], [%1], 16;" :: "r"(s), "l"(g));
}

// ---------------------------------------------------------------------------
// Phase 1a: im2col A[m=(b,np)][kk=jk*256+l] fp16 — transposed x stage.
// Thread owns (np, l8); loops jk=0..8 internally. Index math amortized 9x,
// stores stay fully coalesced (lanes vary l8 -> contiguous 512B per warp).
// ---------------------------------------------------------------------------
#define XP 520

__global__ void prep_a(const float* __restrict__ x) {
    extern __shared__ float xs[];  // [49][520]
    const int b = blockIdx.x;
    const float* xb = x + (size_t)b * CIN * HW;
    for (int i = threadIdx.x; i < CIN * HW; i += blockDim.x) {
        int c = i / HW, hw = i - c * HW;
        xs[hw * XP + c] = xb[i];
    }
    __syncthreads();

    uint4* aout = (uint4*)(Acol_g + (size_t)b * HW * KDIM);
    for (int idx = threadIdx.x; idx < HW * 32; idx += blockDim.x) {
        const int l8 = idx & 31;            // lane (warp-uniform np)
        const int np = idx >> 5;
        const int n = np / 7, p = np - 7 * n;
        const int l0 = l8 * 8;
        uint4* dst = aout + np * (KDIM / 8) + l8;

#pragma unroll
        for (int j = 0; j < 3; j++) {
            const int ha = ((n + 6) % 7) + j - 1;
            const int hb = n + j - 1;
            const bool arow = (ha >= 0) && (ha < 7);
            const bool brow = (hb >= 0) && (hb < 7);
            const float* rowa = xs + (ha * 7) * XP + 256 + l0;
            const float* rowb = xs + (hb * 7) * XP + l0;
#pragma unroll
            for (int k = 0; k < 3; k++) {
                const int pk = p + k;
                const bool pv = (pk >= 1) && (pk <= 7);
                const int w2 = (pk + 5) % 7;
                const bool av = pv && arow;
                const bool bv = pv && brow;

                float4 a0 = {0,0,0,0}, a1 = {0,0,0,0}, b0 = {0,0,0,0}, b1 = {0,0,0,0};
                if (av) {
                    const float4* pa = (const float4*)(rowa + w2 * XP);
                    a0 = pa[0]; a1 = pa[1];
                }
                if (bv) {
                    const float4* pb = (const float4*)(rowb + w2 * XP);
                    b0 = pb[0]; b1 = pb[1];
                }
                __half2 p0 = __floats2half2_rn(a0.x + b0.x, a0.y + b0.y);
                __half2 p1 = __floats2half2_rn(a0.z + b0.z, a0.w + b0.w);
                __half2 p2 = __floats2half2_rn(a1.x + b1.x, a1.y + b1.y);
                __half2 p3 = __floats2half2_rn(a1.z + b1.z, a1.w + b1.w);
                uint4 o;
                o.x = *reinterpret_cast<uint32_t*>(&p0);
                o.y = *reinterpret_cast<uint32_t*>(&p1);
                o.z = *reinterpret_cast<uint32_t*>(&p2);
                o.w = *reinterpret_cast<uint32_t*>(&p3);
                dst[(j * 3 + k) * 32] = o;
            }
        }
    }
}

// ---------------------------------------------------------------------------
// Phase 1b: Whn[i][kk=jk*256+l] = fp16( W[l][j][k][i] )   (K-major per row)
// ---------------------------------------------------------------------------
__global__ void prep_w(const float* __restrict__ W) {
    int t = blockIdx.x * blockDim.x + threadIdx.x;  // over 512 * 1152 half2
    if (t >= NDIM * (KDIM / 2)) return;
    int i   = t / (KDIM / 2);
    int kk2 = t - i * (KDIM / 2);
    int kk  = kk2 * 2;
    int jk  = kk >> 8;
    int l   = kk & 255;
    float v0 = W[(size_t)(l * 9 + jk) * NDIM + i];
    float v1 = W[(size_t)((l + 1) * 9 + jk) * NDIM + i];
    reinterpret_cast<__half2*>(Whn_g)[t] = __floats2half2_rn(v0, v1);
}

// ---------------------------------------------------------------------------
// Phase 2: GEMM out[m][i] = sum_k A[m][k] * Whn[i][k]   (exact R3 version)
// mma.sync m16n8k16, BM=128 BN=128 BK=64, 3-stage cp.async, SW128 smem.
// 8 warps (2x4), warp tile 64x32. Grid (4 bn, 392 bm).
// ---------------------------------------------------------------------------
#define BK 64
#define NC (KDIM / BK)        // 36
#define STG_H 8192            // halfs per stage per operand (128 * 64)
#define DSMEM (3 * 2 * STG_H * 2 + 256)

__device__ __forceinline__ void load_stage(
    const __half* __restrict__ Ag, const __half* __restrict__ Bg,
    uint32_t sA, uint32_t sB, int k0, int tid)
{
#pragma unroll
    for (int q = 0; q < 4; q++) {            // A: 1024 x 16B
        int id = tid + q * 256;
        int r = id >> 3, c = id & 7;
        cpa16(sA + swz((uint32_t)(r * 128 + c * 16)),
              Ag + (size_t)r * KDIM + k0 + c * 8);
    }
#pragma unroll
    for (int q = 0; q < 4; q++) {            // B: 1024 x 16B
        int id = tid + q * 256;
        int r = id >> 3, c = id & 7;
        cpa16(sB + swz((uint32_t)(r * 128 + c * 16)),
              Bg + (size_t)r * KDIM + k0 + c * 8);
    }
    asm volatile("cp.async.commit_group;" ::: "memory");
}

__global__ __launch_bounds__(256, 2) void gemm_f16(float* __restrict__ out) {
    extern __shared__ char dsm[];
    const uint32_t sbase = (s2u(dsm) + 127) & ~127u;

    const int bn   = blockIdx.x;     // 0..3
    const int bm   = blockIdx.y;     // 0..391
    const int tid  = threadIdx.x;
    const int wid  = tid >> 5;
    const int lane = tid & 31;
    const int wm   = wid >> 2;       // 0..1
    const int wn   = wid & 3;        // 0..3

    const __half* Ag = Acol_g + (size_t)bm * 128 * KDIM;
    const __half* Bg = Whn_g + (size_t)bn * 128 * KDIM;

    uint32_t sA[3], sB[3];
#pragma unroll
    for (int s = 0; s < 3; s++) {
        sA[s] = sbase + s * (STG_H * 2);
        sB[s] = sbase + (3 + s) * (STG_H * 2);
    }

    float acc[4][4][4];
#pragma unroll
    for (int a = 0; a < 4; a++)
#pragma unroll
        for (int b = 0; b < 4; b++)
#pragma unroll
            for (int c = 0; c < 4; c++) acc[a][b][c] = 0.f;

    load_stage(Ag, Bg, sA[0], sB[0], 0, tid);
    load_stage(Ag, Bg, sA[1], sB[1], BK, tid);

    for (int t = 0; t < NC; t++) {
        if (t == NC - 1) asm volatile("cp.async.wait_group 0;" ::: "memory");
        else             asm volatile("cp.async.wait_group 1;" ::: "memory");
        __syncthreads();

        if (t + 2 < NC)
            load_stage(Ag, Bg, sA[(t + 2) % 3], sB[(t + 2) % 3], (t + 2) * BK, tid);

        const uint32_t cA = sA[t % 3];
        const uint32_t cB = sB[t % 3];
#pragma unroll
        for (int ks = 0; ks < 4; ks++) {
            const uint32_t kboff = ks * 32;  // 16 halfs = 32 B
            uint32_t a[4][4];
#pragma unroll
            for (int mi = 0; mi < 4; mi++) {
                uint32_t full = cA + swz((uint32_t)((wm * 64 + mi * 16 + (lane & 15)) * 128
                                                    + kboff + (lane >> 4) * 16));
                asm volatile("ldmatrix.sync.aligned.m8n8.x4.shared.b16 {%0,%1,%2,%3}, [%4];"
                             : "=r"(a[mi][0]), "=r"(a[mi][1]), "=r"(a[mi][2]), "=r"(a[mi][3])
                             : "r"(full));
            }
            uint32_t bf[4][2];
#pragma unroll
            for (int ni = 0; ni < 4; ni++) {
                uint32_t full = cB + swz((uint32_t)((wn * 32 + ni * 8 + (lane & 7)) * 128
                                                    + kboff + ((lane >> 3) & 1) * 16));
                asm volatile("ldmatrix.sync.aligned.m8n8.x2.shared.b16 {%0,%1}, [%2];"
                             : "=r"(bf[ni][0]), "=r"(bf[ni][1])
                             : "r"(full));
            }
#pragma unroll
            for (int mi = 0; mi < 4; mi++)
#pragma unroll
                for (int ni = 0; ni < 4; ni++) {
                    asm volatile(
                        "mma.sync.aligned.m16n8k16.row.col.f32.f16.f16.f32 "
                        "{%0,%1,%2,%3}, {%4,%5,%6,%7}, {%8,%9}, {%0,%1,%2,%3};"
                        : "+f"(acc[mi][ni][0]), "+f"(acc[mi][ni][1]),
                          "+f"(acc[mi][ni][2]), "+f"(acc[mi][ni][3])
                        : "r"(a[mi][0]), "r"(a[mi][1]), "r"(a[mi][2]), "r"(a[mi][3]),
                          "r"(bf[ni][0]), "r"(bf[ni][1]));
                }
        }
        __syncthreads();
    }

    // Epilogue: scatter to out[(b*512 + i)*49 + np]
    const int m_base = bm * 128 + wm * 64;
    const int i_base = bn * 128 + wn * 32;
#pragma unroll
    for (int mi = 0; mi < 4; mi++) {
#pragma unroll
        for (int ni = 0; ni < 4; ni++) {
            int row0 = m_base + mi * 16 + (lane >> 2);
            int col0 = i_base + ni * 8 + (lane & 3) * 2;
#pragma unroll
            for (int h = 0; h < 2; h++) {
                int m  = row0 + h * 8;
                int b  = m / 49;
                int np = m - b * 49;
                float* o = out + (size_t)(b * NDIM + col0) * 49 + np;
                o[0]  = acc[mi][ni][h * 2 + 0];
                o[49] = acc[mi][ni][h * 2 + 1];
            }
        }
    }
}

// ---------------------------------------------------------------------------
extern "C" void kernel_launch(void* const* d_in, const int* in_sizes, int n_in,
                              void* d_out, int out_size) {
    const float* x = (const float*)d_in[0];   // (1024, 512, 7, 7)
    const float* W = (const float*)d_in[1];   // (256, 3, 3, 512)
    float* out = (float*)d_out;               // (1024, 512, 7, 7)

    cudaFuncSetAttribute(prep_a, cudaFuncAttributeMaxDynamicSharedMemorySize,
                         HW * XP * (int)sizeof(float));
    cudaFuncSetAttribute(gemm_f16, cudaFuncAttributeMaxDynamicSharedMemorySize, DSMEM);

    prep_a<<<BATCH, 512, HW * XP * sizeof(float)>>>(x);
    prep_w<<<(NDIM * (KDIM / 2) + 255) / 256, 256>>>(W);
    gemm_f16<<<dim3(NDIM / 128, MDIM / 128), 256, DSMEM>>>(out);
}

// round 7
// speedup vs baseline: 1.4754x; 1.0516x over previous
#include <cuda_runtime.h>
#include <cuda_fp16.h>
#include <cstdint>

#define BATCH 1024
#define CIN   512
#define HW    49
#define KDIM  2304          // 9 * 256
#define MDIM  50176         // 1024 * 49
#define NDIM  512

// Scratch (module-load allocation; legal per harness rules)
__device__ __align__(16) __half Acol_g[(size_t)MDIM * KDIM];   // [m][kk]   231 MB
__device__ __align__(16) __half Whn_g[(size_t)NDIM * KDIM];    // [i][kk]   2.3 MB (K-major)

// ---------------------------------------------------------------------------
// helpers
// ---------------------------------------------------------------------------
__device__ __forceinline__ uint32_t s2u(const void* p) {
    uint32_t a;
    asm("{ .reg .u64 t; cvta.to.shared.u64 t, %1; cvt.u32.u64 %0, t; }" : "=r"(a) : "l"(p));
    return a;
}
__device__ __forceinline__ uint32_t swz(uint32_t o) { return o ^ ((o >> 3) & 0x70); }

__device__ __forceinline__ void cpa16(uint32_t s, const void* g) {
    asm volatile("cp.async.cg.shared.global [%0], [%1], 16;" :: "r"(s), "l"(g));
}

// ---------------------------------------------------------------------------
// Phase 1a: im2col A[m=(b,np)][kk=jk*256+l] fp16 — transposed x stage (R3 form).
// XP=524: staging STS lane-stride = 524 words = 12 mod 32 (gcd 4) -> 4-way
// conflicts instead of 8-way at 520; rows stay float4-aligned (524 % 4 == 0).
// ---------------------------------------------------------------------------
#define XP 524

__global__ void prep_a(const float* __restrict__ x) {
    extern __shared__ float xs[];  // [49][524]
    const int b = blockIdx.x;
    const float* xb = x + (size_t)b * CIN * HW;
    for (int i = threadIdx.x; i < CIN * HW; i += blockDim.x) {
        int c = i / HW, hw = i - c * HW;
        xs[hw * XP + c] = xb[i];
    }
    __syncthreads();

    __half* aout = Acol_g + (size_t)b * HW * KDIM;
    for (int idx = threadIdx.x; idx < HW * 9 * 32; idx += blockDim.x) {
        int l8 = idx & 31;
        int r  = idx >> 5;
        int jk = r % 9;
        int np = r / 9;
        int j = jk / 3, k = jk - 3 * j;
        int n = np / 7, p = np - 7 * n;

        int pk = p + k;
        bool pv = (pk >= 1 && pk <= 7);
        int w2 = (pk + 5) % 7;
        int ha = ((n + 6) % 7) + j - 1;
        int hb = n + j - 1;
        bool av = pv && (ha >= 0) && (ha < 7);
        bool bv = pv && (hb >= 0) && (hb < 7);

        int l0 = l8 * 8;
        float4 a0 = {0,0,0,0}, a1 = {0,0,0,0}, b0 = {0,0,0,0}, b1 = {0,0,0,0};
        if (av) {
            const float4* pa = (const float4*)(xs + (ha * 7 + w2) * XP + 256 + l0);
            a0 = pa[0]; a1 = pa[1];
        }
        if (bv) {
            const float4* pb = (const float4*)(xs + (hb * 7 + w2) * XP + l0);
            b0 = pb[0]; b1 = pb[1];
        }
        __half2 p0 = __floats2half2_rn(a0.x + b0.x, a0.y + b0.y);
        __half2 p1 = __floats2half2_rn(a0.z + b0.z, a0.w + b0.w);
        __half2 p2 = __floats2half2_rn(a1.x + b1.x, a1.y + b1.y);
        __half2 p3 = __floats2half2_rn(a1.z + b1.z, a1.w + b1.w);
        uint4 o;
        o.x = *reinterpret_cast<uint32_t*>(&p0);
        o.y = *reinterpret_cast<uint32_t*>(&p1);
        o.z = *reinterpret_cast<uint32_t*>(&p2);
        o.w = *reinterpret_cast<uint32_t*>(&p3);
        reinterpret_cast<uint4*>(aout)[np * (KDIM / 8) + jk * 32 + l8] = o;
    }
}

// ---------------------------------------------------------------------------
// Phase 1b: Whn[i][kk=jk*256+l] = fp16( W[l][j][k][i] )   (K-major per row)
// ---------------------------------------------------------------------------
__global__ void prep_w(const float* __restrict__ W) {
    int t = blockIdx.x * blockDim.x + threadIdx.x;  // over 512 * 1152 half2
    if (t >= NDIM * (KDIM / 2)) return;
    int i   = t / (KDIM / 2);
    int kk2 = t - i * (KDIM / 2);
    int kk  = kk2 * 2;
    int jk  = kk >> 8;
    int l   = kk & 255;
    float v0 = W[(size_t)(l * 9 + jk) * NDIM + i];
    float v1 = W[(size_t)((l + 1) * 9 + jk) * NDIM + i];
    reinterpret_cast<__half2*>(Whn_g)[t] = __floats2half2_rn(v0, v1);
}

// ---------------------------------------------------------------------------
// Phase 2: GEMM out[m][i] = sum_k A[m][k] * Whn[i][k]
// mma.sync m16n8k16, BM=128 BN=128 BK=64, 3-stage cp.async, SW128 smem.
// 8 warps (2x4), warp tile 64x32. One barrier per mainloop iteration
// (top barrier protects stage (t+2)%3 == read-stage of t-1). Coalesced
// epilogue via smem transpose obuf[i][m].
// ---------------------------------------------------------------------------
#define BK 64
#define NC (KDIM / BK)        // 36
#define STG_H 8192            // halfs per stage per operand (128 * 64)
#define DSMEM (3 * 2 * STG_H * 2 + 256)   // 98560 B (>= 128*132*4 epilogue buf)

__device__ __forceinline__ void load_stage(
    const __half* __restrict__ Ag, const __half* __restrict__ Bg,
    uint32_t sA, uint32_t sB, int k0, int tid)
{
#pragma unroll
    for (int q = 0; q < 4; q++) {            // A: 1024 x 16B
        int id = tid + q * 256;
        int r = id >> 3, c = id & 7;
        cpa16(sA + swz((uint32_t)(r * 128 + c * 16)),
              Ag + (size_t)r * KDIM + k0 + c * 8);
    }
#pragma unroll
    for (int q = 0; q < 4; q++) {            // B: 1024 x 16B
        int id = tid + q * 256;
        int r = id >> 3, c = id & 7;
        cpa16(sB + swz((uint32_t)(r * 128 + c * 16)),
              Bg + (size_t)r * KDIM + k0 + c * 8);
    }
    asm volatile("cp.async.commit_group;" ::: "memory");
}

__global__ __launch_bounds__(256, 2) void gemm_f16(float* __restrict__ out) {
    extern __shared__ char dsm[];
    const uint32_t sbase = (s2u(dsm) + 127) & ~127u;

    const int bn   = blockIdx.x;     // 0..3
    const int bm   = blockIdx.y;     // 0..391
    const int tid  = threadIdx.x;
    const int wid  = tid >> 5;
    const int lane = tid & 31;
    const int wm   = wid >> 2;       // 0..1
    const int wn   = wid & 3;        // 0..3

    const __half* Ag = Acol_g + (size_t)bm * 128 * KDIM;
    const __half* Bg = Whn_g + (size_t)bn * 128 * KDIM;

    uint32_t sA[3], sB[3];
#pragma unroll
    for (int s = 0; s < 3; s++) {
        sA[s] = sbase + s * (STG_H * 2);
        sB[s] = sbase + (3 + s) * (STG_H * 2);
    }

    float acc[4][4][4];
#pragma unroll
    for (int a = 0; a < 4; a++)
#pragma unroll
        for (int b = 0; b < 4; b++)
#pragma unroll
            for (int c = 0; c < 4; c++) acc[a][b][c] = 0.f;

    load_stage(Ag, Bg, sA[0], sB[0], 0, tid);
    load_stage(Ag, Bg, sA[1], sB[1], BK, tid);

    for (int t = 0; t < NC; t++) {
        if (t == NC - 1) asm volatile("cp.async.wait_group 0;" ::: "memory");
        else             asm volatile("cp.async.wait_group 1;" ::: "memory");
        __syncthreads();

        if (t + 2 < NC)
            load_stage(Ag, Bg, sA[(t + 2) % 3], sB[(t + 2) % 3], (t + 2) * BK, tid);

        const uint32_t cA = sA[t % 3];
        const uint32_t cB = sB[t % 3];
#pragma unroll
        for (int ks = 0; ks < 4; ks++) {
            const uint32_t kboff = ks * 32;  // 16 halfs = 32 B
            uint32_t a[4][4];
#pragma unroll
            for (int mi = 0; mi < 4; mi++) {
                uint32_t full = cA + swz((uint32_t)((wm * 64 + mi * 16 + (lane & 15)) * 128
                                                    + kboff + (lane >> 4) * 16));
                asm volatile("ldmatrix.sync.aligned.m8n8.x4.shared.b16 {%0,%1,%2,%3}, [%4];"
                             : "=r"(a[mi][0]), "=r"(a[mi][1]), "=r"(a[mi][2]), "=r"(a[mi][3])
                             : "r"(full));
            }
            uint32_t bf[4][2];
#pragma unroll
            for (int ni = 0; ni < 4; ni++) {
                uint32_t full = cB + swz((uint32_t)((wn * 32 + ni * 8 + (lane & 7)) * 128
                                                    + kboff + ((lane >> 3) & 1) * 16));
                asm volatile("ldmatrix.sync.aligned.m8n8.x2.shared.b16 {%0,%1}, [%2];"
                             : "=r"(bf[ni][0]), "=r"(bf[ni][1])
                             : "r"(full));
            }
#pragma unroll
            for (int mi = 0; mi < 4; mi++)
#pragma unroll
                for (int ni = 0; ni < 4; ni++) {
                    asm volatile(
                        "mma.sync.aligned.m16n8k16.row.col.f32.f16.f16.f32 "
                        "{%0,%1,%2,%3}, {%4,%5,%6,%7}, {%8,%9}, {%0,%1,%2,%3};"
                        : "+f"(acc[mi][ni][0]), "+f"(acc[mi][ni][1]),
                          "+f"(acc[mi][ni][2]), "+f"(acc[mi][ni][3])
                        : "r"(a[mi][0]), "r"(a[mi][1]), "r"(a[mi][2]), "r"(a[mi][3]),
                          "r"(bf[ni][0]), "r"(bf[ni][1]));
                }
        }
        // no bottom barrier: top barrier of t+1 protects stage reuse
    }

    // ---- Epilogue: smem transpose -> coalesced stores ----
    __syncthreads();                       // all mainloop smem reads done
    float* obuf = (float*)dsm;             // [128 i][132 m] = 67584 B
#pragma unroll
    for (int mi = 0; mi < 4; mi++) {
#pragma unroll
        for (int ni = 0; ni < 4; ni++) {
            int ml = wm * 64 + mi * 16 + (lane >> 2);
            int il = wn * 32 + ni * 8 + (lane & 3) * 2;
            obuf[il * 132 + ml]            = acc[mi][ni][0];
            obuf[(il + 1) * 132 + ml]      = acc[mi][ni][1];
            obuf[il * 132 + ml + 8]        = acc[mi][ni][2];
            obuf[(il + 1) * 132 + ml + 8]  = acc[mi][ni][3];
        }
    }
    __syncthreads();

    const int i_base = bn * 128;
    const int m_base = bm * 128;
    for (int idx = tid; idx < 128 * 128; idx += 256) {
        int il = idx >> 7, ml = idx & 127;
        int m  = m_base + ml;
        int b  = m / 49;
        int np = m - b * 49;
        out[(size_t)(b * NDIM + i_base + il) * 49 + np] = obuf[il * 132 + ml];
    }
}

// ---------------------------------------------------------------------------
extern "C" void kernel_launch(void* const* d_in, const int* in_sizes, int n_in,
                              void* d_out, int out_size) {
    const float* x = (const float*)d_in[0];   // (1024, 512, 7, 7)
    const float* W = (const float*)d_in[1];   // (256, 3, 3, 512)
    float* out = (float*)d_out;               // (1024, 512, 7, 7)

    cudaFuncSetAttribute(prep_a, cudaFuncAttributeMaxDynamicSharedMemorySize,
                         HW * XP * (int)sizeof(float));
    cudaFuncSetAttribute(gemm_f16, cudaFuncAttributeMaxDynamicSharedMemorySize, DSMEM);

    prep_a<<<BATCH, 512, HW * XP * sizeof(float)>>>(x);
    prep_w<<<(NDIM * (KDIM / 2) + 255) / 256, 256>>>(W);
    gemm_f16<<<dim3(NDIM / 128, MDIM / 128), 256, DSMEM>>>(out);
}

// round 8
// speedup vs baseline: 1.5193x; 1.0298x over previous
#include <cuda_runtime.h>
#include <cuda_fp16.h>
#include <cstdint>

#define BATCH 1024
#define CIN   512
#define HW    49
#define KDIM  2304          // 9 * 256
#define MDIM  50176         // 1024 * 49
#define NDIM  512

// Scratch (module-load allocation; legal per harness rules)
// G[b][j][n][w][l]: folded two-group shifted sum; l innermost (256 halfs = 512B rows)
__device__ __align__(16) __half G_g[(size_t)BATCH * 3 * HW * 256];   // 77 MB
__device__ __align__(16) __half Whn_g[(size_t)NDIM * KDIM];          // [i][kk] K-major

// ---------------------------------------------------------------------------
// helpers
// ---------------------------------------------------------------------------
__device__ __forceinline__ uint32_t s2u(const void* p) {
    uint32_t a;
    asm("{ .reg .u64 t; cvta.to.shared.u64 t, %1; cvt.u32.u64 %0, t; }" : "=r"(a) : "l"(p));
    return a;
}
__device__ __forceinline__ uint32_t swz(uint32_t o) { return o ^ ((o >> 3) & 0x70); }

// ---------------------------------------------------------------------------
// Phase 1a: G[b][j][n*7+w][l] = [hb valid]*x[b,l,hb,w] + [ha valid]*x[b,256+l,ha,w]
//   hb = n+j-1, ha = ((n+6)%7)+j-1.  Transposed x stage; coalesced uint4 stores.
// ---------------------------------------------------------------------------
#define XP 524

__global__ void prep_g(const float* __restrict__ x) {
    extern __shared__ float xs[];  // [49][524]
    const int b = blockIdx.x;
    const float* xb = x + (size_t)b * CIN * HW;
    for (int i = threadIdx.x; i < CIN * HW; i += blockDim.x) {
        int c = i / HW, hw = i - c * HW;
        xs[hw * XP + c] = xb[i];
    }
    __syncthreads();

    uint4* gout = (uint4*)(G_g + (size_t)b * 3 * HW * 256);
    for (int idx = threadIdx.x; idx < 3 * HW * 32; idx += blockDim.x) {
        const int l8 = idx & 31;
        const int rr = idx >> 5;          // 0..146 : (j, n*7+w)
        const int j  = rr / 49;
        const int nw = rr - j * 49;
        const int n  = nw / 7;
        const int w  = nw - 7 * n;

        const int hb = n + j - 1;
        const int ha = ((n + 6) % 7) + j - 1;
        const bool bv = (hb >= 0) && (hb < 7);
        const bool av = (ha >= 0) && (ha < 7);

        const int l0 = l8 * 8;
        float4 a0 = {0,0,0,0}, a1 = {0,0,0,0}, b0 = {0,0,0,0}, b1 = {0,0,0,0};
        if (av) {
            const float4* pa = (const float4*)(xs + (ha * 7 + w) * XP + 256 + l0);
            a0 = pa[0]; a1 = pa[1];
        }
        if (bv) {
            const float4* pb = (const float4*)(xs + (hb * 7 + w) * XP + l0);
            b0 = pb[0]; b1 = pb[1];
        }
        __half2 p0 = __floats2half2_rn(a0.x + b0.x, a0.y + b0.y);
        __half2 p1 = __floats2half2_rn(a0.z + b0.z, a0.w + b0.w);
        __half2 p2 = __floats2half2_rn(a1.x + b1.x, a1.y + b1.y);
        __half2 p3 = __floats2half2_rn(a1.z + b1.z, a1.w + b1.w);
        uint4 o;
        o.x = *reinterpret_cast<uint32_t*>(&p0);
        o.y = *reinterpret_cast<uint32_t*>(&p1);
        o.z = *reinterpret_cast<uint32_t*>(&p2);
        o.w = *reinterpret_cast<uint32_t*>(&p3);
        gout[rr * 32 + l8] = o;
    }
}

// ---------------------------------------------------------------------------
// Phase 1b: Whn[i][kk=jk*256+l] = fp16( W[l][j][k][i] )   (K-major per row)
// ---------------------------------------------------------------------------
__global__ void prep_w(const float* __restrict__ W) {
    int t = blockIdx.x * blockDim.x + threadIdx.x;  // over 512 * 1152 half2
    if (t >= NDIM * (KDIM / 2)) return;
    int i   = t / (KDIM / 2);
    int kk2 = t - i * (KDIM / 2);
    int kk  = kk2 * 2;
    int jk  = kk >> 8;
    int l   = kk & 255;
    float v0 = W[(size_t)(l * 9 + jk) * NDIM + i];
    float v1 = W[(size_t)((l + 1) * 9 + jk) * NDIM + i];
    reinterpret_cast<__half2*>(Whn_g)[t] = __floats2half2_rn(v0, v1);
}

// ---------------------------------------------------------------------------
// Phase 2: fused-im2col GEMM  out[m][i] = sum_k A[m][k] * Whn[i][k]
// A-tile rows streamed straight from G with cp.async (src-size 0 => zero fill
// for masked (p,k)).  Mainloop identical to R6: mma.sync m16n8k16, BM=128
// BN=128 BK=64, 3-stage, SW128 smem, warp tile 64x32, smem-transpose epilogue.
// ---------------------------------------------------------------------------
#define BK 64
#define NC (KDIM / BK)        // 36
#define STG_H 8192            // halfs per stage per operand (128 * 64)
#define DSMEM (3 * 2 * STG_H * 2 + 256)

struct ARow {
    const __half* g[4];   // per q: G base for this row (b,n and c*8 folded in)
    int p[4];
};

__device__ __forceinline__ void load_stage(
    const ARow& ar, const __half* __restrict__ Bg,
    uint32_t sA, uint32_t sB, int chunk, int tid)
{
    const int jk = chunk >> 2;
    const int l0 = (chunk & 3) << 6;
    const int j  = (jk * 11) >> 5;        // jk/3 for jk in [0,8]
    const int k  = jk - 3 * j;
    const int off0 = j * (49 * 256) + l0;
    const int r0 = tid >> 3;
    const int c16 = (tid & 7) * 16;
#pragma unroll
    for (int q = 0; q < 4; q++) {         // A: 128 rows x 8 chunks of 16B
        const int p = ar.p[q];
        int w2 = p + k + 5; if (w2 >= 7) w2 -= 7;
        const uint32_t vsz = ((unsigned)(p + k - 1) <= 6u) ? 16u : 0u;
        const uint32_t dst = sA + swz((uint32_t)((r0 + q * 32) * 128 + c16));
        const __half* src = ar.g[q] + off0 + w2 * 256;
        asm volatile("cp.async.cg.shared.global [%0], [%1], 16, %2;"
                     :: "r"(dst), "l"(src), "r"(vsz));
    }
    const int k0 = chunk * BK;
#pragma unroll
    for (int q = 0; q < 4; q++) {         // B: 1024 x 16B
        int id = tid + q * 256;
        int r = id >> 3, c = id & 7;
        asm volatile("cp.async.cg.shared.global [%0], [%1], 16;"
                     :: "r"(sB + swz((uint32_t)(r * 128 + c * 16))),
                        "l"(Bg + (size_t)r * KDIM + k0 + c * 8));
    }
    asm volatile("cp.async.commit_group;" ::: "memory");
}

__global__ __launch_bounds__(256, 2) void gemm_f16(float* __restrict__ out) {
    extern __shared__ char dsm[];
    const uint32_t sbase = (s2u(dsm) + 127) & ~127u;

    const int bn   = blockIdx.x;     // 0..3
    const int bm   = blockIdx.y;     // 0..391
    const int tid  = threadIdx.x;
    const int wid  = tid >> 5;
    const int lane = tid & 31;
    const int wm   = wid >> 2;       // 0..1
    const int wn   = wid & 3;        // 0..3

    const __half* Bg = Whn_g + (size_t)bn * 128 * KDIM;

    // per-thread A-row constants (rows r0+32q, fixed byte-column c*8)
    ARow ar;
    {
        const int r0 = tid >> 3;
        const int c8 = (tid & 7) * 8;
#pragma unroll
        for (int q = 0; q < 4; q++) {
            int m  = bm * 128 + r0 + q * 32;
            int b  = m / 49;
            int np = m - b * 49;
            int n  = np / 7;
            ar.p[q] = np - 7 * n;
            ar.g[q] = G_g + ((size_t)b * 147 + n * 7) * 256 + c8;
        }
    }

    uint32_t sA[3], sB[3];
#pragma unroll
    for (int s = 0; s < 3; s++) {
        sA[s] = sbase + s * (STG_H * 2);
        sB[s] = sbase + (3 + s) * (STG_H * 2);
    }

    float acc[4][4][4];
#pragma unroll
    for (int a = 0; a < 4; a++)
#pragma unroll
        for (int b = 0; b < 4; b++)
#pragma unroll
            for (int c = 0; c < 4; c++) acc[a][b][c] = 0.f;

    load_stage(ar, Bg, sA[0], sB[0], 0, tid);
    load_stage(ar, Bg, sA[1], sB[1], 1, tid);

    for (int t = 0; t < NC; t++) {
        if (t == NC - 1) asm volatile("cp.async.wait_group 0;" ::: "memory");
        else             asm volatile("cp.async.wait_group 1;" ::: "memory");
        __syncthreads();

        if (t + 2 < NC)
            load_stage(ar, Bg, sA[(t + 2) % 3], sB[(t + 2) % 3], t + 2, tid);

        const uint32_t cA = sA[t % 3];
        const uint32_t cB = sB[t % 3];
#pragma unroll
        for (int ks = 0; ks < 4; ks++) {
            const uint32_t kboff = ks * 32;  // 16 halfs = 32 B
            uint32_t a[4][4];
#pragma unroll
            for (int mi = 0; mi < 4; mi++) {
                uint32_t full = cA + swz((uint32_t)((wm * 64 + mi * 16 + (lane & 15)) * 128
                                                    + kboff + (lane >> 4) * 16));
                asm volatile("ldmatrix.sync.aligned.m8n8.x4.shared.b16 {%0,%1,%2,%3}, [%4];"
                             : "=r"(a[mi][0]), "=r"(a[mi][1]), "=r"(a[mi][2]), "=r"(a[mi][3])
                             : "r"(full));
            }
            uint32_t bf[4][2];
#pragma unroll
            for (int ni = 0; ni < 4; ni++) {
                uint32_t full = cB + swz((uint32_t)((wn * 32 + ni * 8 + (lane & 7)) * 128
                                                    + kboff + ((lane >> 3) & 1) * 16));
                asm volatile("ldmatrix.sync.aligned.m8n8.x2.shared.b16 {%0,%1}, [%2];"
                             : "=r"(bf[ni][0]), "=r"(bf[ni][1])
                             : "r"(full));
            }
#pragma unroll
            for (int mi = 0; mi < 4; mi++)
#pragma unroll
                for (int ni = 0; ni < 4; ni++) {
                    asm volatile(
                        "mma.sync.aligned.m16n8k16.row.col.f32.f16.f16.f32 "
                        "{%0,%1,%2,%3}, {%4,%5,%6,%7}, {%8,%9}, {%0,%1,%2,%3};"
                        : "+f"(acc[mi][ni][0]), "+f"(acc[mi][ni][1]),
                          "+f"(acc[mi][ni][2]), "+f"(acc[mi][ni][3])
                        : "r"(a[mi][0]), "r"(a[mi][1]), "r"(a[mi][2]), "r"(a[mi][3]),
                          "r"(bf[ni][0]), "r"(bf[ni][1]));
                }
        }
        // no bottom barrier: top barrier of t+1 protects stage reuse
    }

    // ---- Epilogue: smem transpose -> coalesced stores ----
    __syncthreads();
    float* obuf = (float*)dsm;             // [128 i][132 m]
#pragma unroll
    for (int mi = 0; mi < 4; mi++) {
#pragma unroll
        for (int ni = 0; ni < 4; ni++) {
            int ml = wm * 64 + mi * 16 + (lane >> 2);
            int il = wn * 32 + ni * 8 + (lane & 3) * 2;
            obuf[il * 132 + ml]            = acc[mi][ni][0];
            obuf[(il + 1) * 132 + ml]      = acc[mi][ni][1];
            obuf[il * 132 + ml + 8]        = acc[mi][ni][2];
            obuf[(il + 1) * 132 + ml + 8]  = acc[mi][ni][3];
        }
    }
    __syncthreads();

    const int i_base = bn * 128;
    const int m_base = bm * 128;
    for (int idx = tid; idx < 128 * 128; idx += 256) {
        int il = idx >> 7, ml = idx & 127;
        int m  = m_base + ml;
        int b  = m / 49;
        int np = m - b * 49;
        out[(size_t)(b * NDIM + i_base + il) * 49 + np] = obuf[il * 132 + ml];
    }
}

// ---------------------------------------------------------------------------
extern "C" void kernel_launch(void* const* d_in, const int* in_sizes, int n_in,
                              void* d_out, int out_size) {
    const float* x = (const float*)d_in[0];   // (1024, 512, 7, 7)
    const float* W = (const float*)d_in[1];   // (256, 3, 3, 512)
    float* out = (float*)d_out;               // (1024, 512, 7, 7)

    cudaFuncSetAttribute(prep_g, cudaFuncAttributeMaxDynamicSharedMemorySize,
                         HW * XP * (int)sizeof(float));
    cudaFuncSetAttribute(gemm_f16, cudaFuncAttributeMaxDynamicSharedMemorySize, DSMEM);

    prep_g<<<BATCH, 512, HW * XP * sizeof(float)>>>(x);
    prep_w<<<(NDIM * (KDIM / 2) + 255) / 256, 256>>>(W);
    gemm_f16<<<dim3(NDIM / 128, MDIM / 128), 256, DSMEM>>>(out);
}

// round 9
// speedup vs baseline: 1.5394x; 1.0132x over previous
#include <cuda_runtime.h>
#include <cuda_fp16.h>
#include <cstdint>

#define BATCH 1024
#define CIN   512
#define HW    49
#define KDIM  2304          // 9 * 256
#define MDIM  50176         // 1024 * 49
#define NDIM  512

// Scratch (module-load allocation; legal per harness rules)
// G[b][j][n][w][l]: folded two-group shifted sum; l innermost (256 halfs = 512B rows)
__device__ __align__(16) __half G_g[(size_t)BATCH * 3 * HW * 256];   // 77 MB
__device__ __align__(16) __half Whn_g[(size_t)NDIM * KDIM];          // [i][kk] K-major

// ---------------------------------------------------------------------------
// helpers
// ---------------------------------------------------------------------------
__device__ __forceinline__ uint32_t s2u(const void* p) {
    uint32_t a;
    asm("{ .reg .u64 t; cvta.to.shared.u64 t, %1; cvt.u32.u64 %0, t; }" : "=r"(a) : "l"(p));
    return a;
}
__device__ __forceinline__ uint32_t swz(uint32_t o) { return o ^ ((o >> 3) & 0x70); }

// ---------------------------------------------------------------------------
// Phase 1a: G[b][j][n*7+w][l] = [hb valid]*x[b,l,hb,w] + [ha valid]*x[b,256+l,ha,w]
//   hb = n+j-1, ha = ((n+6)%7)+j-1.
// 2 blocks per batch (channel halves): 51KB stage -> 2 blocks/SM occupancy.
// Block (b, half) stages channels [half*128,+128) and [256+half*128,+128):
//   xs[hw][cc], cc 0..127 = group0 half, 128..255 = group1 half.
// Each block writes a contiguous 256B run of every G row -> coalesced.
// ---------------------------------------------------------------------------
#define XP2 260

__global__ void prep_g(const float* __restrict__ x) {
    extern __shared__ float xs[];  // [49][260]
    const int b    = blockIdx.x >> 1;
    const int half = blockIdx.x & 1;
    const float* xb = x + (size_t)b * CIN * HW;

    for (int i = threadIdx.x; i < 256 * HW; i += blockDim.x) {
        int cc = i / HW;
        int hw = i - cc * HW;
        int c  = (cc < 128) ? (half * 128 + cc) : (128 + half * 128 + cc);  // +256 group offset
        xs[hw * XP2 + cc] = xb[c * HW + hw];
    }
    __syncthreads();

    uint4* gout = (uint4*)(G_g + (size_t)b * 3 * HW * 256);
    for (int idx = threadIdx.x; idx < 3 * HW * 16; idx += blockDim.x) {
        const int l8 = idx & 15;          // local 16B chunk within this half
        const int rr = idx >> 4;          // 0..146 : (j, n*7+w)
        const int j  = rr / 49;
        const int nw = rr - j * 49;
        const int n  = nw / 7;
        const int w  = nw - 7 * n;

        const int hb = n + j - 1;
        const int ha = ((n + 6) % 7) + j - 1;
        const bool bv = (hb >= 0) && (hb < 7);
        const bool av = (ha >= 0) && (ha < 7);

        const int l0 = l8 * 8;
        float4 a0 = {0,0,0,0}, a1 = {0,0,0,0}, b0 = {0,0,0,0}, b1 = {0,0,0,0};
        if (av) {
            const float4* pa = (const float4*)(xs + (ha * 7 + w) * XP2 + 128 + l0);
            a0 = pa[0]; a1 = pa[1];
        }
        if (bv) {
            const float4* pb = (const float4*)(xs + (hb * 7 + w) * XP2 + l0);
            b0 = pb[0]; b1 = pb[1];
        }
        __half2 p0 = __floats2half2_rn(a0.x + b0.x, a0.y + b0.y);
        __half2 p1 = __floats2half2_rn(a0.z + b0.z, a0.w + b0.w);
        __half2 p2 = __floats2half2_rn(a1.x + b1.x, a1.y + b1.y);
        __half2 p3 = __floats2half2_rn(a1.z + b1.z, a1.w + b1.w);
        uint4 o;
        o.x = *reinterpret_cast<uint32_t*>(&p0);
        o.y = *reinterpret_cast<uint32_t*>(&p1);
        o.z = *reinterpret_cast<uint32_t*>(&p2);
        o.w = *reinterpret_cast<uint32_t*>(&p3);
        gout[rr * 32 + half * 16 + l8] = o;
    }
}

// ---------------------------------------------------------------------------
// Phase 1b: Whn[i][kk=jk*256+l] = fp16( W[l][j][k][i] ) via smem tile transpose.
// Grid (9 jk, 4 lt, 8 it), block 256, tile 64l x 64i. Coalesced both sides.
// ---------------------------------------------------------------------------
__global__ void prep_w(const float* __restrict__ W) {
    __shared__ float tile[64][65];
    const int jk = blockIdx.x;
    const int lt = blockIdx.y;
    const int it = blockIdx.z;

    for (int i = threadIdx.x; i < 64 * 64; i += blockDim.x) {
        int ll = i >> 6, ii = i & 63;
        tile[ll][ii] = W[((size_t)(lt * 64 + ll) * 9 + jk) * NDIM + it * 64 + ii];
    }
    __syncthreads();

    __half2* out2 = (__half2*)Whn_g;
    for (int i = threadIdx.x; i < 64 * 32; i += blockDim.x) {
        int ii = i >> 5, l2 = i & 31;
        float v0 = tile[l2 * 2][ii];
        float v1 = tile[l2 * 2 + 1][ii];
        out2[(size_t)(it * 64 + ii) * (KDIM / 2) + jk * 128 + lt * 32 + l2] =
            __floats2half2_rn(v0, v1);
    }
}

// ---------------------------------------------------------------------------
// Phase 2: fused-im2col GEMM  out[m][i] = sum_k A[m][k] * Whn[i][k]
// (identical to R7 — proven 295us)
// ---------------------------------------------------------------------------
#define BK 64
#define NC (KDIM / BK)        // 36
#define STG_H 8192            // halfs per stage per operand (128 * 64)
#define DSMEM (3 * 2 * STG_H * 2 + 256)

struct ARow {
    const __half* g[4];   // per q: G base for this row (b,n and c*8 folded in)
    int p[4];
};

__device__ __forceinline__ void load_stage(
    const ARow& ar, const __half* __restrict__ Bg,
    uint32_t sA, uint32_t sB, int chunk, int tid)
{
    const int jk = chunk >> 2;
    const int l0 = (chunk & 3) << 6;
    const int j  = (jk * 11) >> 5;        // jk/3 for jk in [0,8]
    const int k  = jk - 3 * j;
    const int off0 = j * (49 * 256) + l0;
    const int r0 = tid >> 3;
    const int c16 = (tid & 7) * 16;
#pragma unroll
    for (int q = 0; q < 4; q++) {         // A: 128 rows x 8 chunks of 16B
        const int p = ar.p[q];
        int w2 = p + k + 5; if (w2 >= 7) w2 -= 7;
        const uint32_t vsz = ((unsigned)(p + k - 1) <= 6u) ? 16u : 0u;
        const uint32_t dst = sA + swz((uint32_t)((r0 + q * 32) * 128 + c16));
        const __half* src = ar.g[q] + off0 + w2 * 256;
        asm volatile("cp.async.cg.shared.global [%0], [%1], 16, %2;"
                     :: "r"(dst), "l"(src), "r"(vsz));
    }
    const int k0 = chunk * BK;
#pragma unroll
    for (int q = 0; q < 4; q++) {         // B: 1024 x 16B
        int id = tid + q * 256;
        int r = id >> 3, c = id & 7;
        asm volatile("cp.async.cg.shared.global [%0], [%1], 16;"
                     :: "r"(sB + swz((uint32_t)(r * 128 + c * 16))),
                        "l"(Bg + (size_t)r * KDIM + k0 + c * 8));
    }
    asm volatile("cp.async.commit_group;" ::: "memory");
}

__global__ __launch_bounds__(256, 2) void gemm_f16(float* __restrict__ out) {
    extern __shared__ char dsm[];
    const uint32_t sbase = (s2u(dsm) + 127) & ~127u;

    const int bn   = blockIdx.x;     // 0..3
    const int bm   = blockIdx.y;     // 0..391
    const int tid  = threadIdx.x;
    const int wid  = tid >> 5;
    const int lane = tid & 31;
    const int wm   = wid >> 2;       // 0..1
    const int wn   = wid & 3;        // 0..3

    const __half* Bg = Whn_g + (size_t)bn * 128 * KDIM;

    ARow ar;
    {
        const int r0 = tid >> 3;
        const int c8 = (tid & 7) * 8;
#pragma unroll
        for (int q = 0; q < 4; q++) {
            int m  = bm * 128 + r0 + q * 32;
            int b  = m / 49;
            int np = m - b * 49;
            int n  = np / 7;
            ar.p[q] = np - 7 * n;
            ar.g[q] = G_g + ((size_t)b * 147 + n * 7) * 256 + c8;
        }
    }

    uint32_t sA[3], sB[3];
#pragma unroll
    for (int s = 0; s < 3; s++) {
        sA[s] = sbase + s * (STG_H * 2);
        sB[s] = sbase + (3 + s) * (STG_H * 2);
    }

    float acc[4][4][4];
#pragma unroll
    for (int a = 0; a < 4; a++)
#pragma unroll
        for (int b = 0; b < 4; b++)
#pragma unroll
            for (int c = 0; c < 4; c++) acc[a][b][c] = 0.f;

    load_stage(ar, Bg, sA[0], sB[0], 0, tid);
    load_stage(ar, Bg, sA[1], sB[1], 1, tid);

    for (int t = 0; t < NC; t++) {
        if (t == NC - 1) asm volatile("cp.async.wait_group 0;" ::: "memory");
        else             asm volatile("cp.async.wait_group 1;" ::: "memory");
        __syncthreads();

        if (t + 2 < NC)
            load_stage(ar, Bg, sA[(t + 2) % 3], sB[(t + 2) % 3], t + 2, tid);

        const uint32_t cA = sA[t % 3];
        const uint32_t cB = sB[t % 3];
#pragma unroll
        for (int ks = 0; ks < 4; ks++) {
            const uint32_t kboff = ks * 32;  // 16 halfs = 32 B
            uint32_t a[4][4];
#pragma unroll
            for (int mi = 0; mi < 4; mi++) {
                uint32_t full = cA + swz((uint32_t)((wm * 64 + mi * 16 + (lane & 15)) * 128
                                                    + kboff + (lane >> 4) * 16));
                asm volatile("ldmatrix.sync.aligned.m8n8.x4.shared.b16 {%0,%1,%2,%3}, [%4];"
                             : "=r"(a[mi][0]), "=r"(a[mi][1]), "=r"(a[mi][2]), "=r"(a[mi][3])
                             : "r"(full));
            }
            uint32_t bf[4][2];
#pragma unroll
            for (int ni = 0; ni < 4; ni++) {
                uint32_t full = cB + swz((uint32_t)((wn * 32 + ni * 8 + (lane & 7)) * 128
                                                    + kboff + ((lane >> 3) & 1) * 16));
                asm volatile("ldmatrix.sync.aligned.m8n8.x2.shared.b16 {%0,%1}, [%2];"
                             : "=r"(bf[ni][0]), "=r"(bf[ni][1])
                             : "r"(full));
            }
#pragma unroll
            for (int mi = 0; mi < 4; mi++)
#pragma unroll
                for (int ni = 0; ni < 4; ni++) {
                    asm volatile(
                        "mma.sync.aligned.m16n8k16.row.col.f32.f16.f16.f32 "
                        "{%0,%1,%2,%3}, {%4,%5,%6,%7}, {%8,%9}, {%0,%1,%2,%3};"
                        : "+f"(acc[mi][ni][0]), "+f"(acc[mi][ni][1]),
                          "+f"(acc[mi][ni][2]), "+f"(acc[mi][ni][3])
                        : "r"(a[mi][0]), "r"(a[mi][1]), "r"(a[mi][2]), "r"(a[mi][3]),
                          "r"(bf[ni][0]), "r"(bf[ni][1]));
                }
        }
        // no bottom barrier: top barrier of t+1 protects stage reuse
    }

    // ---- Epilogue: smem transpose -> coalesced stores ----
    __syncthreads();
    float* obuf = (float*)dsm;             // [128 i][132 m]
#pragma unroll
    for (int mi = 0; mi < 4; mi++) {
#pragma unroll
        for (int ni = 0; ni < 4; ni++) {
            int ml = wm * 64 + mi * 16 + (lane >> 2);
            int il = wn * 32 + ni * 8 + (lane & 3) * 2;
            obuf[il * 132 + ml]            = acc[mi][ni][0];
            obuf[(il + 1) * 132 + ml]      = acc[mi][ni][1];
            obuf[il * 132 + ml + 8]        = acc[mi][ni][2];
            obuf[(il + 1) * 132 + ml + 8]  = acc[mi][ni][3];
        }
    }
    __syncthreads();

    const int i_base = bn * 128;
    const int m_base = bm * 128;
    for (int idx = tid; idx < 128 * 128; idx += 256) {
        int il = idx >> 7, ml = idx & 127;
        int m  = m_base + ml;
        int b  = m / 49;
        int np = m - b * 49;
        out[(size_t)(b * NDIM + i_base + il) * 49 + np] = obuf[il * 132 + ml];
    }
}

// ---------------------------------------------------------------------------
extern "C" void kernel_launch(void* const* d_in, const int* in_sizes, int n_in,
                              void* d_out, int out_size) {
    const float* x = (const float*)d_in[0];   // (1024, 512, 7, 7)
    const float* W = (const float*)d_in[1];   // (256, 3, 3, 512)
    float* out = (float*)d_out;               // (1024, 512, 7, 7)

    cudaFuncSetAttribute(prep_g, cudaFuncAttributeMaxDynamicSharedMemorySize,
                         HW * XP2 * (int)sizeof(float));
    cudaFuncSetAttribute(gemm_f16, cudaFuncAttributeMaxDynamicSharedMemorySize, DSMEM);

    prep_g<<<2 * BATCH, 512, HW * XP2 * sizeof(float)>>>(x);
    prep_w<<<dim3(9, 4, 8), 256>>>(W);
    gemm_f16<<<dim3(NDIM / 128, MDIM / 128), 256, DSMEM>>>(out);
}

// round 10
// speedup vs baseline: 1.5560x; 1.0108x over previous
#include <cuda_runtime.h>
#include <cuda_fp16.h>
#include <cstdint>

#define BATCH 1024
#define CIN   512
#define HW    49
#define KDIM  2304          // 9 * 256
#define MDIM  50176         // 1024 * 49
#define NDIM  512

// Scratch (module-load allocation; legal per harness rules)
// G[b][j][n][w][l]: folded two-group shifted sum; l innermost (256 halfs = 512B rows)
__device__ __align__(16) __half G_g[(size_t)BATCH * 3 * HW * 256];   // 77 MB
__device__ __align__(16) __half Whn_g[(size_t)NDIM * KDIM];          // [i][kk] K-major

// ---------------------------------------------------------------------------
// helpers
// ---------------------------------------------------------------------------
__device__ __forceinline__ uint32_t s2u(const void* p) {
    uint32_t a;
    asm("{ .reg .u64 t; cvta.to.shared.u64 t, %1; cvt.u32.u64 %0, t; }" : "=r"(a) : "l"(p));
    return a;
}
__device__ __forceinline__ uint32_t swz(uint32_t o) { return o ^ ((o >> 3) & 0x70); }

// ---------------------------------------------------------------------------
// Phase 1 (merged): blocks [0, 2048) build G; blocks [2048, 2336) transpose W.
//
// prep_g part: G[b][j][n*7+w][l] = [hb]*x[b,l,hb,w] + [ha]*x[b,256+l,ha,w]
//   hb = n+j-1, ha = ((n+6)%7)+j-1.  2 blocks per batch (channel halves).
//   2-item batched inner loop: all 8 predicated float4 LDS issued before any
//   conversion -> MLP ~8 to hide LDS latency.
// prep_w part: Whn[i][jk*256+l] via 64x64 smem tile transpose (64x65 floats).
// ---------------------------------------------------------------------------
#define XP2 260
#define GWORK (3 * HW * 16)   // 2352 items per prep_g block

__global__ __launch_bounds__(512, 2) void prep(const float* __restrict__ x,
                                               const float* __restrict__ W) {
    extern __shared__ float sm[];

    if (blockIdx.x < 2 * BATCH) {
        // ----------------- prep_g -----------------
        const int b    = blockIdx.x >> 1;
        const int half = blockIdx.x & 1;
        const float* xb = x + (size_t)b * CIN * HW;

        for (int i = threadIdx.x; i < 256 * HW; i += blockDim.x) {
            int cc = i / HW;
            int hw = i - cc * HW;
            int c  = (cc < 128) ? (half * 128 + cc) : (128 + half * 128 + cc);
            sm[hw * XP2 + cc] = xb[c * HW + hw];
        }
        __syncthreads();

        uint4* gout = (uint4*)(G_g + (size_t)b * 3 * HW * 256);

        for (int base = threadIdx.x; base < GWORK; base += 1024) {
            // ---- decompose both items ----
            int idx0 = base;
            int idx1 = base + 512;
            const bool has1 = (idx1 < GWORK);

            int l8_0 = idx0 & 15,  rr0 = idx0 >> 4;
            int l8_1 = idx1 & 15,  rr1 = idx1 >> 4;

            int j0 = rr0 / 49, nw0 = rr0 - j0 * 49, n0 = nw0 / 7, w0 = nw0 - 7 * n0;
            int j1 = rr1 / 49, nw1 = rr1 - j1 * 49, n1 = nw1 / 7, w1 = nw1 - 7 * n1;

            int hb0 = n0 + j0 - 1, ha0 = ((n0 + 6) % 7) + j0 - 1;
            int hb1 = n1 + j1 - 1, ha1 = ((n1 + 6) % 7) + j1 - 1;
            bool bv0 = (hb0 >= 0) && (hb0 < 7), av0 = (ha0 >= 0) && (ha0 < 7);
            bool bv1 = has1 && (hb1 >= 0) && (hb1 < 7);
            bool av1 = has1 && (ha1 >= 0) && (ha1 < 7);

            const float4* pa0 = (const float4*)(sm + (ha0 * 7 + w0) * XP2 + 128 + l8_0 * 8);
            const float4* pb0 = (const float4*)(sm + (hb0 * 7 + w0) * XP2 + l8_0 * 8);
            const float4* pa1 = (const float4*)(sm + (ha1 * 7 + w1) * XP2 + 128 + l8_1 * 8);
            const float4* pb1 = (const float4*)(sm + (hb1 * 7 + w1) * XP2 + l8_1 * 8);

            // ---- issue all loads (predicated) ----
            float4 a00 = {0,0,0,0}, a01 = {0,0,0,0}, b00 = {0,0,0,0}, b01 = {0,0,0,0};
            float4 a10 = {0,0,0,0}, a11 = {0,0,0,0}, b10 = {0,0,0,0}, b11 = {0,0,0,0};
            if (av0) { a00 = pa0[0]; a01 = pa0[1]; }
            if (bv0) { b00 = pb0[0]; b01 = pb0[1]; }
            if (av1) { a10 = pa1[0]; a11 = pa1[1]; }
            if (bv1) { b10 = pb1[0]; b11 = pb1[1]; }

            // ---- convert + store item 0 ----
            {
                __half2 p0 = __floats2half2_rn(a00.x + b00.x, a00.y + b00.y);
                __half2 p1 = __floats2half2_rn(a00.z + b00.z, a00.w + b00.w);
                __half2 p2 = __floats2half2_rn(a01.x + b01.x, a01.y + b01.y);
                __half2 p3 = __floats2half2_rn(a01.z + b01.z, a01.w + b01.w);
                uint4 o;
                o.x = *reinterpret_cast<uint32_t*>(&p0);
                o.y = *reinterpret_cast<uint32_t*>(&p1);
                o.z = *reinterpret_cast<uint32_t*>(&p2);
                o.w = *reinterpret_cast<uint32_t*>(&p3);
                gout[rr0 * 32 + half * 16 + l8_0] = o;
            }
            // ---- convert + store item 1 ----
            if (has1) {
                __half2 p0 = __floats2half2_rn(a10.x + b10.x, a10.y + b10.y);
                __half2 p1 = __floats2half2_rn(a10.z + b10.z, a10.w + b10.w);
                __half2 p2 = __floats2half2_rn(a11.x + b11.x, a11.y + b11.y);
                __half2 p3 = __floats2half2_rn(a11.z + b11.z, a11.w + b11.w);
                uint4 o;
                o.x = *reinterpret_cast<uint32_t*>(&p0);
                o.y = *reinterpret_cast<uint32_t*>(&p1);
                o.z = *reinterpret_cast<uint32_t*>(&p2);
                o.w = *reinterpret_cast<uint32_t*>(&p3);
                gout[rr1 * 32 + half * 16 + l8_1] = o;
            }
        }
    } else {
        // ----------------- prep_w (tile transpose) -----------------
        float* tile = sm;                       // [64][65]
        const int bid2 = blockIdx.x - 2 * BATCH;   // 0..287
        const int jk = bid2 / 32;
        const int r  = bid2 - jk * 32;
        const int lt = r >> 3;
        const int it = r & 7;

        for (int i = threadIdx.x; i < 64 * 64; i += blockDim.x) {
            int ll = i >> 6, ii = i & 63;
            tile[ll * 65 + ii] = W[((size_t)(lt * 64 + ll) * 9 + jk) * NDIM + it * 64 + ii];
        }
        __syncthreads();

        __half2* out2 = (__half2*)Whn_g;
        for (int i = threadIdx.x; i < 64 * 32; i += blockDim.x) {
            int ii = i >> 5, l2 = i & 31;
            float v0 = tile[(l2 * 2) * 65 + ii];
            float v1 = tile[(l2 * 2 + 1) * 65 + ii];
            out2[(size_t)(it * 64 + ii) * (KDIM / 2) + jk * 128 + lt * 32 + l2] =
                __floats2half2_rn(v0, v1);
        }
    }
}

// ---------------------------------------------------------------------------
// Phase 2: fused-im2col GEMM  out[m][i] = sum_k A[m][k] * Whn[i][k]
// (identical to R7/R8 — proven)
// ---------------------------------------------------------------------------
#define BK 64
#define NC (KDIM / BK)        // 36
#define STG_H 8192            // halfs per stage per operand (128 * 64)
#define DSMEM (3 * 2 * STG_H * 2 + 256)

struct ARow {
    const __half* g[4];   // per q: G base for this row (b,n and c*8 folded in)
    int p[4];
};

__device__ __forceinline__ void load_stage(
    const ARow& ar, const __half* __restrict__ Bg,
    uint32_t sA, uint32_t sB, int chunk, int tid)
{
    const int jk = chunk >> 2;
    const int l0 = (chunk & 3) << 6;
    const int j  = (jk * 11) >> 5;        // jk/3 for jk in [0,8]
    const int k  = jk - 3 * j;
    const int off0 = j * (49 * 256) + l0;
    const int r0 = tid >> 3;
    const int c16 = (tid & 7) * 16;
#pragma unroll
    for (int q = 0; q < 4; q++) {         // A: 128 rows x 8 chunks of 16B
        const int p = ar.p[q];
        int w2 = p + k + 5; if (w2 >= 7) w2 -= 7;
        const uint32_t vsz = ((unsigned)(p + k - 1) <= 6u) ? 16u : 0u;
        const uint32_t dst = sA + swz((uint32_t)((r0 + q * 32) * 128 + c16));
        const __half* src = ar.g[q] + off0 + w2 * 256;
        asm volatile("cp.async.cg.shared.global [%0], [%1], 16, %2;"
                     :: "r"(dst), "l"(src), "r"(vsz));
    }
    const int k0 = chunk * BK;
#pragma unroll
    for (int q = 0; q < 4; q++) {         // B: 1024 x 16B
        int id = tid + q * 256;
        int r = id >> 3, c = id & 7;
        asm volatile("cp.async.cg.shared.global [%0], [%1], 16;"
                     :: "r"(sB + swz((uint32_t)(r * 128 + c * 16))),
                        "l"(Bg + (size_t)r * KDIM + k0 + c * 8));
    }
    asm volatile("cp.async.commit_group;" ::: "memory");
}

__global__ __launch_bounds__(256, 2) void gemm_f16(float* __restrict__ out) {
    extern __shared__ char dsm[];
    const uint32_t sbase = (s2u(dsm) + 127) & ~127u;

    const int bn   = blockIdx.x;     // 0..3
    const int bm   = blockIdx.y;     // 0..391
    const int tid  = threadIdx.x;
    const int wid  = tid >> 5;
    const int lane = tid & 31;
    const int wm   = wid >> 2;       // 0..1
    const int wn   = wid & 3;        // 0..3

    const __half* Bg = Whn_g + (size_t)bn * 128 * KDIM;

    ARow ar;
    {
        const int r0 = tid >> 3;
        const int c8 = (tid & 7) * 8;
#pragma unroll
        for (int q = 0; q < 4; q++) {
            int m  = bm * 128 + r0 + q * 32;
            int b  = m / 49;
            int np = m - b * 49;
            int n  = np / 7;
            ar.p[q] = np - 7 * n;
            ar.g[q] = G_g + ((size_t)b * 147 + n * 7) * 256 + c8;
        }
    }

    uint32_t sA[3], sB[3];
#pragma unroll
    for (int s = 0; s < 3; s++) {
        sA[s] = sbase + s * (STG_H * 2);
        sB[s] = sbase + (3 + s) * (STG_H * 2);
    }

    float acc[4][4][4];
#pragma unroll
    for (int a = 0; a < 4; a++)
#pragma unroll
        for (int b = 0; b < 4; b++)
#pragma unroll
            for (int c = 0; c < 4; c++) acc[a][b][c] = 0.f;

    load_stage(ar, Bg, sA[0], sB[0], 0, tid);
    load_stage(ar, Bg, sA[1], sB[1], 1, tid);

    for (int t = 0; t < NC; t++) {
        if (t == NC - 1) asm volatile("cp.async.wait_group 0;" ::: "memory");
        else             asm volatile("cp.async.wait_group 1;" ::: "memory");
        __syncthreads();

        if (t + 2 < NC)
            load_stage(ar, Bg, sA[(t + 2) % 3], sB[(t + 2) % 3], t + 2, tid);

        const uint32_t cA = sA[t % 3];
        const uint32_t cB = sB[t % 3];
#pragma unroll
        for (int ks = 0; ks < 4; ks++) {
            const uint32_t kboff = ks * 32;  // 16 halfs = 32 B
            uint32_t a[4][4];
#pragma unroll
            for (int mi = 0; mi < 4; mi++) {
                uint32_t full = cA + swz((uint32_t)((wm * 64 + mi * 16 + (lane & 15)) * 128
                                                    + kboff + (lane >> 4) * 16));
                asm volatile("ldmatrix.sync.aligned.m8n8.x4.shared.b16 {%0,%1,%2,%3}, [%4];"
                             : "=r"(a[mi][0]), "=r"(a[mi][1]), "=r"(a[mi][2]), "=r"(a[mi][3])
                             : "r"(full));
            }
            uint32_t bf[4][2];
#pragma unroll
            for (int ni = 0; ni < 4; ni++) {
                uint32_t full = cB + swz((uint32_t)((wn * 32 + ni * 8 + (lane & 7)) * 128
                                                    + kboff + ((lane >> 3) & 1) * 16));
                asm volatile("ldmatrix.sync.aligned.m8n8.x2.shared.b16 {%0,%1}, [%2];"
                             : "=r"(bf[ni][0]), "=r"(bf[ni][1])
                             : "r"(full));
            }
#pragma unroll
            for (int mi = 0; mi < 4; mi++)
#pragma unroll
                for (int ni = 0; ni < 4; ni++) {
                    asm volatile(
                        "mma.sync.aligned.m16n8k16.row.col.f32.f16.f16.f32 "
                        "{%0,%1,%2,%3}, {%4,%5,%6,%7}, {%8,%9}, {%0,%1,%2,%3};"
                        : "+f"(acc[mi][ni][0]), "+f"(acc[mi][ni][1]),
                          "+f"(acc[mi][ni][2]), "+f"(acc[mi][ni][3])
                        : "r"(a[mi][0]), "r"(a[mi][1]), "r"(a[mi][2]), "r"(a[mi][3]),
                          "r"(bf[ni][0]), "r"(bf[ni][1]));
                }
        }
        // no bottom barrier: top barrier of t+1 protects stage reuse
    }

    // ---- Epilogue: smem transpose -> coalesced stores ----
    __syncthreads();
    float* obuf = (float*)dsm;             // [128 i][132 m]
#pragma unroll
    for (int mi = 0; mi < 4; mi++) {
#pragma unroll
        for (int ni = 0; ni < 4; ni++) {
            int ml = wm * 64 + mi * 16 + (lane >> 2);
            int il = wn * 32 + ni * 8 + (lane & 3) * 2;
            obuf[il * 132 + ml]            = acc[mi][ni][0];
            obuf[(il + 1) * 132 + ml]      = acc[mi][ni][1];
            obuf[il * 132 + ml + 8]        = acc[mi][ni][2];
            obuf[(il + 1) * 132 + ml + 8]  = acc[mi][ni][3];
        }
    }
    __syncthreads();

    const int i_base = bn * 128;
    const int m_base = bm * 128;
    for (int idx = tid; idx < 128 * 128; idx += 256) {
        int il = idx >> 7, ml = idx & 127;
        int m  = m_base + ml;
        int b  = m / 49;
        int np = m - b * 49;
        out[(size_t)(b * NDIM + i_base + il) * 49 + np] = obuf[il * 132 + ml];
    }
}

// ---------------------------------------------------------------------------
extern "C" void kernel_launch(void* const* d_in, const int* in_sizes, int n_in,
                              void* d_out, int out_size) {
    const float* x = (const float*)d_in[0];   // (1024, 512, 7, 7)
    const float* W = (const float*)d_in[1];   // (256, 3, 3, 512)
    float* out = (float*)d_out;               // (1024, 512, 7, 7)

    cudaFuncSetAttribute(prep, cudaFuncAttributeMaxDynamicSharedMemorySize,
                         HW * XP2 * (int)sizeof(float));
    cudaFuncSetAttribute(gemm_f16, cudaFuncAttributeMaxDynamicSharedMemorySize, DSMEM);

    prep<<<2 * BATCH + 288, 512, HW * XP2 * sizeof(float)>>>(x, W);
    gemm_f16<<<dim3(NDIM / 128, MDIM / 128), 256, DSMEM>>>(out);
}